// round 9
// baseline (speedup 1.0000x reference)
#include <cuda_runtime.h>
#include <cuda_fp16.h>
#include <math.h>

#define IN_CH  128
#define ED_CH  64
#define HID_CH 256
#define K_CLS  1000
#define MAXN   50000
#define MAXB   128

// transposed fp16 weights: [n][k] layouts (offsets in half elements)
#define WE_T_OFF  0          // 128 x 64
#define W1_T_OFF  8192       // 256 x 128
#define W2_T_OFF  40960      // 256 x 256
#define WG1_T_OFF 106496     // 128 x 256

#define STAGE_BYTES 36864    // edge: one (A 18KB + B 18KB) fp16 stage
#define EDGE_DSM    (36864 + 65536)   // 1 stage + 128x128 f32 x-stage

// fused MLP smem layout (bytes)
#define OFF_AS  0                       // h stage: 128 x 136 halves = 34816
#define OFF_T   34816                   // t:  128 x 264 halves = 67584
#define OFF_H2  (34816 + 67584)         // h2: 128 x 264 halves = 67584
#define OFF_B   (OFF_H2 + 67584)        // 3 B stages x 18432
#define FUSE_DSM (OFF_B + 3 * 18432)    // 225280 B = 220 KB

// ---------------- scratch (static device globals; no allocation) ----------------
__device__ float    g_agg[MAXN * IN_CH];     // init = x, edge adds messages -> becomes h
__device__ float    g_h2[MAXN * HID_CH];
__device__ float    g_gate[MAXN];
__device__ unsigned g_gmax[MAXB];
__device__ float    g_denom[MAXB];
__device__ float    g_pnum[MAXB * HID_CH];
__device__ __half   g_wt[139264];
__device__ int      g_is64;

// ---------------- helpers ----------------
__device__ __forceinline__ unsigned fenc(float f) {
    unsigned u = __float_as_uint(f);
    return (u & 0x80000000u) ? ~u : (u | 0x80000000u);
}
__device__ __forceinline__ float fdec(unsigned u) {
    return __uint_as_float((u & 0x80000000u) ? (u ^ 0x80000000u) : ~u);
}
__device__ __forceinline__ void red4(float* p, float a, float b, float c, float d) {
    asm volatile("red.global.add.v4.f32 [%0], {%1,%2,%3,%4};"
                 :: "l"(p), "f"(a), "f"(b), "f"(c), "f"(d) : "memory");
}
__device__ __forceinline__ long long load_index(const void* p, long i, int is64) {
    if (is64) return ((const long long*)p)[i];
    return (long long)((const int*)p)[i];
}
__device__ __forceinline__ unsigned f2h2(float a, float b) {
    __half2 h = __floats2half2_rn(a, b);
    return *(unsigned*)&h;
}
__device__ __forceinline__ void mma16(float* c, const unsigned* a, const unsigned* b) {
    asm volatile("mma.sync.aligned.m16n8k16.row.col.f32.f16.f16.f32 "
                 "{%0,%1,%2,%3}, {%4,%5,%6,%7}, {%8,%9}, {%0,%1,%2,%3};"
                 : "+f"(c[0]), "+f"(c[1]), "+f"(c[2]), "+f"(c[3])
                 : "r"(a[0]), "r"(a[1]), "r"(a[2]), "r"(a[3]), "r"(b[0]), "r"(b[1]));
}
__device__ __forceinline__ void ldsm4(unsigned* r, unsigned addr) {
    asm volatile("ldmatrix.sync.aligned.m8n8.x4.shared.b16 {%0,%1,%2,%3}, [%4];"
                 : "=r"(r[0]), "=r"(r[1]), "=r"(r[2]), "=r"(r[3]) : "r"(addr));
}
__device__ __forceinline__ void cpasync16(unsigned saddr, const void* g) {
    asm volatile("cp.async.cg.shared.global [%0], [%1], 16;" :: "r"(saddr), "l"(g) : "memory");
}
__device__ __forceinline__ void cp_commit() {
    asm volatile("cp.async.commit_group;" ::: "memory");
}
template <int N> __device__ __forceinline__ void cp_wait() {
    asm volatile("cp.async.wait_group %0;" :: "n"(N) : "memory");
}

// edge-kernel fragment addresses (A: [m][k] stride 72, B: [n][k] stride 72; 8-warp 4x2 grid)
__device__ __forceinline__ void frag_addrs(unsigned as_b, unsigned bs_b, int lane,
                                           int wm, int wn, unsigned* aa, unsigned* bb) {
    #pragma unroll
    for (int mi = 0; mi < 2; mi++)
        aa[mi] = as_b + ((wm * 32 + mi * 16 + (lane & 15)) * 72 + (lane >> 4) * 8) * 2;
    #pragma unroll
    for (int nj = 0; nj < 4; nj++)
        bb[nj] = bs_b + ((wn * 64 + nj * 16 + (lane & 7) + ((lane >> 4) & 1) * 8) * 72
                         + ((lane >> 3) & 1) * 8) * 2;
}

// ---------------- weight prep: Wt16[n][k] = half(W[k][n]) ----------------
__global__ void prep_kernel(const float* __restrict__ We, const float* __restrict__ W1,
                            const float* __restrict__ W2, const float* __restrict__ Wg1) {
    __shared__ float t[32][33];
    const float* W; int K, N, off;
    switch (blockIdx.z) {
        case 0: W = We;  K = ED_CH;  N = IN_CH;  off = WE_T_OFF;  break;
        case 1: W = W1;  K = IN_CH;  N = HID_CH; off = W1_T_OFF;  break;
        case 2: W = W2;  K = HID_CH; N = HID_CH; off = W2_T_OFF;  break;
        default:W = Wg1; K = HID_CH; N = 128;    off = WG1_T_OFF; break;
    }
    int n0 = blockIdx.x * 32, k0 = blockIdx.y * 32;
    if (n0 >= N || k0 >= K) return;
    __half* dst = g_wt + off;
    for (int i = threadIdx.y; i < 32; i += 8)
        t[i][threadIdx.x] = W[(size_t)(k0 + i) * N + n0 + threadIdx.x];
    __syncthreads();
    for (int i = threadIdx.y; i < 32; i += 8)
        dst[(size_t)(n0 + i) * K + k0 + threadIdx.x] = __float2half(t[threadIdx.x][i]);
}

// ---------------- init: g_agg = x, zero pool accumulators, sniff index dtype ----------------
__global__ void init_kernel(const float* __restrict__ x, const int* __restrict__ ei, int n) {
    int stride = gridDim.x * blockDim.x;
    int i = blockIdx.x * blockDim.x + threadIdx.x;
    int n4 = n * IN_CH / 4;
    for (int j = i; j < n4; j += stride) ((float4*)g_agg)[j] = ((const float4*)x)[j];
    if (i < MAXB * HID_CH) g_pnum[i] = 0.f;
    if (i < MAXB) { g_denom[i] = 0.f; g_gmax[i] = 0u; }
    if (i == 0) {
        int nz = 0;
        #pragma unroll 8
        for (int k = 0; k < 256; k++) nz += (ei[2 * k + 1] != 0);
        g_is64 = (nz < 16) ? 1 : 0;
    }
}

// ---------------- edge phase: fp16 MMA + cp.async x-prefetch + fused relu/scatter ----------------
__global__ void __launch_bounds__(256) edge_mma(
    const float* __restrict__ eattr, const void* __restrict__ ei,
    const float* __restrict__ x, const float* __restrict__ be, int E)
{
    extern __shared__ char dsm[];
    __half* AsH = (__half*)dsm;                    // [128*72]
    float*  Cs  = (float*)dsm;                     // overlay [64*132]
    float*  Xs  = (float*)(dsm + STAGE_BYTES);     // [128*128]
    __shared__ int s_src[128], s_dst[128];

    const int tid = threadIdx.x;
    const int lane = tid & 31, warp = tid >> 5;
    const int wm = warp & 3, wn = warp >> 2;
    const int r0 = lane >> 2, c0 = lane & 3;
    const int eb = blockIdx.x * 128;
    const int is64 = g_is64;
    const __half* Wt = g_wt + WE_T_OFF;

    unsigned as_b = (unsigned)__cvta_generic_to_shared(dsm);
    unsigned bs_b = as_b + 18432;
    unsigned xs_b = as_b + STAGE_BYTES;
    unsigned aa[2], bb[4];
    frag_addrs(as_b, bs_b, lane, wm, wn, aa, bb);

    if (tid < 128) {
        int eg = eb + tid;
        if (eg < E) {
            s_src[tid] = (int)load_index(ei, eg, is64);
            s_dst[tid] = (int)load_index(ei, (long)E + eg, is64);
        } else { s_src[tid] = 0; s_dst[tid] = 0; }
    }

    // B: We_t (128n x 64k halves), group 0
    #pragma unroll
    for (int i = 0; i < 4; i++) {
        int f = tid + i * 256;
        int n = f >> 3, kk = (f & 7) * 8;
        cpasync16(bs_b + (n * 72 + kk) * 2, &Wt[(size_t)n * ED_CH + kk]);
    }
    cp_commit();

    // A: edge_attr (128 x 64), f32 -> half2 into smem
    #pragma unroll
    for (int i = 0; i < 4; i++) {
        int f = tid + i * 256;
        int row = f >> 3, kk = (f & 7) * 8;
        int eg = eb + row;
        float4 v0 = make_float4(0.f, 0.f, 0.f, 0.f), v1 = v0;
        if (eg < E) {
            v0 = *(const float4*)&eattr[(size_t)eg * ED_CH + kk];
            v1 = *(const float4*)&eattr[(size_t)eg * ED_CH + kk + 4];
        }
        uint4 h;
        h.x = f2h2(v0.x, v0.y); h.y = f2h2(v0.z, v0.w);
        h.z = f2h2(v1.x, v1.y); h.w = f2h2(v1.z, v1.w);
        *(uint4*)&AsH[row * 72 + kk] = h;
    }
    __syncthreads();   // s_src visible to all

    // x[src] prefetch: 128 rows x 512B via cp.async, group 1 (hidden under MMA)
    #pragma unroll
    for (int i = 0; i < 16; i++) {
        int f = tid + i * 256;
        int row = f >> 5, seg = f & 31;
        cpasync16(xs_b + (row * 128 + seg * 4) * 4, &x[(size_t)s_src[row] * IN_CH + seg * 4]);
    }
    cp_commit();

    cp_wait<1>();      // B arrived (x may still be in flight)
    __syncthreads();

    float acc[2][8][4];
    #pragma unroll
    for (int mi = 0; mi < 2; mi++)
        #pragma unroll
        for (int ni = 0; ni < 8; ni++)
            #pragma unroll
            for (int q = 0; q < 4; q++) acc[mi][ni][q] = 0.f;

    #pragma unroll
    for (int ks = 0; ks < 4; ks++) {
        unsigned a[2][4], b[4][4];
        ldsm4(a[0], aa[0] + ks * 32);
        ldsm4(a[1], aa[1] + ks * 32);
        #pragma unroll
        for (int j = 0; j < 4; j++) ldsm4(b[j], bb[j] + ks * 32);
        #pragma unroll
        for (int mi = 0; mi < 2; mi++)
            #pragma unroll
            for (int ni = 0; ni < 8; ni++)
                mma16(acc[mi][ni], a[mi], &b[ni >> 1][(ni & 1) * 2]);
    }
    cp_wait<0>();      // x arrived
    __syncthreads();   // MMA smem reads done -> Cs overlay safe

    const float4 bev = *(const float4*)&be[lane * 4];

    // epilogue in 2 phases of 64 edge-rows (Cs overlays A/B stage; Xs separate)
    #pragma unroll
    for (int p = 0; p < 2; p++) {
        if ((wm >> 1) == p) {
            #pragma unroll
            for (int mi = 0; mi < 2; mi++)
                #pragma unroll
                for (int ni = 0; ni < 8; ni++) {
                    int r = (wm & 1) * 32 + mi * 16 + r0;
                    int col = wn * 64 + ni * 8 + 2 * c0;
                    Cs[r * 132 + col]           = acc[mi][ni][0];
                    Cs[r * 132 + col + 1]       = acc[mi][ni][1];
                    Cs[(r + 8) * 132 + col]     = acc[mi][ni][2];
                    Cs[(r + 8) * 132 + col + 1] = acc[mi][ni][3];
                }
        }
        __syncthreads();
        #pragma unroll
        for (int half = 0; half < 2; half++) {
            #pragma unroll
            for (int j = 0; j < 4; j++) {
                int el = warp * 8 + half * 4 + j;
                int eg = eb + p * 64 + el;
                if (eg < E) {
                    int d = s_dst[p * 64 + el];
                    float4 cv = *(const float4*)&Cs[el * 132 + lane * 4];
                    float4 xv = *(const float4*)&Xs[(p * 64 + el) * 128 + lane * 4];
                    red4(&g_agg[(size_t)d * IN_CH + lane * 4],
                         fmaxf(cv.x + bev.x + xv.x, 0.f),
                         fmaxf(cv.y + bev.y + xv.y, 0.f),
                         fmaxf(cv.z + bev.z + xv.z, 0.f),
                         fmaxf(cv.w + bev.w + xv.w, 0.f));
                }
            }
        }
        __syncthreads();
    }
}

// ---------------- fused node MLP: all 3 GEMMs in one kernel, 128 rows per CTA ----------------
// layer1: T  = relu(h @ W1 + b1)    K=128 N=256  (h from g_agg, staged fp16; T in smem)
// layer2: H2 = T @ W2 + b2          K=256 N=256  (H2 in smem + f32 to g_h2)
// layer3: gate = relu(H2 @ Wg1 + bg1) @ Wg2 + bg2  (register epilogue, gate + gmax)
// 512 threads = 16 warps (4x4 grid of 32x32 warp tiles); 16 weight chunks streamed
// through a 3-buffer cp.async pipeline that never drains.
__global__ void __launch_bounds__(512, 1) fused_mlp(
    const float* __restrict__ b1, const float* __restrict__ b2,
    const float* __restrict__ bg1, const float* __restrict__ Wg2,
    const float* __restrict__ bg2, const void* __restrict__ batch, int M)
{
    extern __shared__ char dsm[];
    __half* Th  = (__half*)(dsm + OFF_T);
    __half* H2h = (__half*)(dsm + OFF_H2);
    float*  part = (float*)(dsm + OFF_AS);   // overlay on As (dead after layer 1)

    const int tid = threadIdx.x;
    const int lane = tid & 31, warp = tid >> 5;
    const int wm = warp & 3, wn = warp >> 2;   // 4 x 4 warp grid
    const int r0 = lane >> 2, c0 = lane & 3;
    const int bm = blockIdx.x * 128;

    unsigned base = (unsigned)__cvta_generic_to_shared(dsm);
    unsigned bstg = base + OFF_B;

    // A-fragment lane addresses per buffer (ldmatrix, [m][k] rows)
    unsigned aAS = base + OFF_AS + (((wm * 32 + (lane & 15)) * 136 + (lane >> 4) * 8) << 1);
    unsigned aT  = base + OFF_T  + (((wm * 32 + (lane & 15)) * 264 + (lane >> 4) * 8) << 1);
    unsigned aH2 = base + OFF_H2 + (((wm * 32 + (lane & 15)) * 264 + (lane >> 4) * 8) << 1);
    // B-fragment offsets within one 18432B stage ([n][k] stride 72)
    unsigned bfr[2];
    #pragma unroll
    for (int nj = 0; nj < 2; nj++)
        bfr[nj] = ((wn * 32 + nj * 16 + (lane & 7) + ((lane >> 4) & 1) * 8) * 72
                   + ((lane >> 3) & 1) * 8) * 2;

    // chunk j -> weight source (16 chunks: 4x W1, 8x W2, 4x Wg1)
    auto issueB = [&](int j) {
        const __half* W; int K, n0, kc;
        if (j < 4)       { W = g_wt + W1_T_OFF;  K = 128; n0 = (j >> 1) << 7; kc = j & 1; }
        else if (j < 12) { int q = j - 4;  W = g_wt + W2_T_OFF;  K = 256; n0 = (q >> 2) << 7; kc = q & 3; }
        else             { int q = j - 12; W = g_wt + WG1_T_OFF; K = 256; n0 = 0; kc = q; }
        unsigned sb = bstg + (unsigned)((j % 3) * 18432);
        #pragma unroll
        for (int i = 0; i < 2; i++) {
            int f = tid + i * 512;
            int n = f >> 3, kk = (f & 7) * 8;
            cpasync16(sb + (n * 72 + kk) * 2, &W[(size_t)(n0 + n) * K + kc * 64 + kk]);
        }
        cp_commit();
    };

    issueB(0); issueB(1);

    // stage h rows: f32 -> fp16 into As (stride 136)
    #pragma unroll
    for (int i = 0; i < 2; i++) {
        int f = tid + i * 512;                 // 0..1023
        int row = f >> 3, seg = (f & 7) * 16;  // 16 halves per item
        int gm = bm + row; if (gm >= M) gm = M - 1;
        const float4* src = (const float4*)&g_agg[(size_t)gm * IN_CH + seg];
        float4 v0 = src[0], v1 = src[1], v2 = src[2], v3 = src[3];
        uint4 ha = make_uint4(f2h2(v0.x, v0.y), f2h2(v0.z, v0.w), f2h2(v1.x, v1.y), f2h2(v1.z, v1.w));
        uint4 hb = make_uint4(f2h2(v2.x, v2.y), f2h2(v2.z, v2.w), f2h2(v3.x, v3.y), f2h2(v3.z, v3.w));
        *(uint4*)(dsm + OFF_AS + (row * 136 + seg) * 2)     = ha;
        *(uint4*)(dsm + OFF_AS + (row * 136 + seg + 8) * 2) = hb;
    }
    __syncthreads();

    float acc[2][4][4];
    #pragma unroll
    for (int mi = 0; mi < 2; mi++)
        #pragma unroll
        for (int ni = 0; ni < 4; ni++)
            #pragma unroll
            for (int q = 0; q < 4; q++) acc[mi][ni][q] = 0.f;

    int next = 2;
    for (int j = 0; j < 16; j++) {
        if (next < 16) { issueB(next); next++; }
        int rem = next - 1 - j;
        if (rem >= 2) cp_wait<2>(); else if (rem == 1) cp_wait<1>(); else cp_wait<0>();
        __syncthreads();

        unsigned abase; unsigned miOff;
        if (j < 4)       { abase = aAS + (unsigned)((j & 1) * 128);        miOff = 136 * 32; }
        else if (j < 12) { abase = aT  + (unsigned)(((j - 4) & 3) * 128);  miOff = 264 * 32; }
        else             { abase = aH2 + (unsigned)((j - 12) * 128);       miOff = 264 * 32; }
        unsigned sb = bstg + (unsigned)((j % 3) * 18432);

        #pragma unroll
        for (int ks = 0; ks < 4; ks++) {
            unsigned a[2][4], b[2][4];
            ldsm4(a[0], abase + ks * 32);
            ldsm4(a[1], abase + miOff + ks * 32);
            ldsm4(b[0], sb + bfr[0] + ks * 32);
            ldsm4(b[1], sb + bfr[1] + ks * 32);
            #pragma unroll
            for (int mi = 0; mi < 2; mi++)
                #pragma unroll
                for (int ni = 0; ni < 4; ni++)
                    mma16(acc[mi][ni], a[mi], &b[ni >> 1][(ni & 1) * 2]);
        }
        __syncthreads();   // protect B-stage reuse (chunk j+3 rewrites stage j%3)

        // ---- group epilogues ----
        if (j == 1 || j == 3) {                 // layer 1 half done -> T
            int nh = (j == 3) ? 128 : 0;
            #pragma unroll
            for (int mi = 0; mi < 2; mi++)
                #pragma unroll
                for (int ni = 0; ni < 4; ni++) {
                    int row = wm * 32 + mi * 16 + r0;
                    int col = nh + wn * 32 + ni * 8 + 2 * c0;
                    float bx = __ldg(&b1[col]), by = __ldg(&b1[col + 1]);
                    *(__half2*)&Th[row * 264 + col] = __floats2half2_rn(
                        fmaxf(acc[mi][ni][0] + bx, 0.f), fmaxf(acc[mi][ni][1] + by, 0.f));
                    *(__half2*)&Th[(row + 8) * 264 + col] = __floats2half2_rn(
                        fmaxf(acc[mi][ni][2] + bx, 0.f), fmaxf(acc[mi][ni][3] + by, 0.f));
                    #pragma unroll
                    for (int q = 0; q < 4; q++) acc[mi][ni][q] = 0.f;
                }
        } else if (j == 7 || j == 11) {         // layer 2 half done -> H2 (+ f32 global)
            int nh = (j == 11) ? 128 : 0;
            #pragma unroll
            for (int mi = 0; mi < 2; mi++)
                #pragma unroll
                for (int ni = 0; ni < 4; ni++) {
                    int row = wm * 32 + mi * 16 + r0;
                    int col = nh + wn * 32 + ni * 8 + 2 * c0;
                    float bx = __ldg(&b2[col]), by = __ldg(&b2[col + 1]);
                    float v0 = acc[mi][ni][0] + bx, v1 = acc[mi][ni][1] + by;
                    float v2 = acc[mi][ni][2] + bx, v3 = acc[mi][ni][3] + by;
                    *(__half2*)&H2h[row * 264 + col]       = __floats2half2_rn(v0, v1);
                    *(__half2*)&H2h[(row + 8) * 264 + col] = __floats2half2_rn(v2, v3);
                    int grow = bm + row;
                    if (grow < M)     *(float2*)&g_h2[(size_t)grow * HID_CH + col]       = make_float2(v0, v1);
                    if (grow + 8 < M) *(float2*)&g_h2[(size_t)(grow + 8) * HID_CH + col] = make_float2(v2, v3);
                    #pragma unroll
                    for (int q = 0; q < 4; q++) acc[mi][ni][q] = 0.f;
                }
        } else if (j == 15) {                   // layer 3 done -> gate (register space)
            #pragma unroll
            for (int mi = 0; mi < 2; mi++) {
                float s_lo = 0.f, s_hi = 0.f;
                #pragma unroll
                for (int ni = 0; ni < 4; ni++) {
                    int col = wn * 32 + ni * 8 + 2 * c0;
                    float bx = __ldg(&bg1[col]), by = __ldg(&bg1[col + 1]);
                    float wx = __ldg(&Wg2[col]),  wy = __ldg(&Wg2[col + 1]);
                    s_lo += fmaxf(acc[mi][ni][0] + bx, 0.f) * wx
                          + fmaxf(acc[mi][ni][1] + by, 0.f) * wy;
                    s_hi += fmaxf(acc[mi][ni][2] + bx, 0.f) * wx
                          + fmaxf(acc[mi][ni][3] + by, 0.f) * wy;
                }
                s_lo += __shfl_xor_sync(0xffffffffu, s_lo, 1);
                s_lo += __shfl_xor_sync(0xffffffffu, s_lo, 2);
                s_hi += __shfl_xor_sync(0xffffffffu, s_hi, 1);
                s_hi += __shfl_xor_sync(0xffffffffu, s_hi, 2);
                if (c0 == 0) {
                    part[wn * 128 + wm * 32 + mi * 16 + r0]     = s_lo;
                    part[wn * 128 + wm * 32 + mi * 16 + r0 + 8] = s_hi;
                }
            }
            __syncthreads();
            if (tid < 128) {
                int row = bm + tid;
                if (row < M) {
                    float g = part[tid] + part[128 + tid] + part[256 + tid] + part[384 + tid] + bg2[0];
                    g_gate[row] = g;
                    int b = (int)load_index(batch, row, g_is64);
                    atomicMax(&g_gmax[b], fenc(g));
                }
            }
        }
    }
}

// ---------------- softmax numerator + weighted sum: warp strips with run-length flush ----------------
__global__ void gsum_kernel(const void* __restrict__ batch, int n) {
    int w = (blockIdx.x * blockDim.x + threadIdx.x) >> 5;
    int lane = threadIdx.x & 31;
    int W = (gridDim.x * blockDim.x) >> 5;
    int L = (n + W - 1) / W;
    int s0 = w * L, e0 = min(s0 + L, n);
    if (s0 >= e0) return;
    const int is64 = g_is64;

    int bcur = (int)load_index(batch, s0, is64);
    float r[8];
    #pragma unroll
    for (int q = 0; q < 8; q++) r[q] = 0.f;
    float dsum = 0.f;

    for (int i = s0; i < e0; i++) {
        int b = (int)load_index(batch, i, is64);
        if (b != bcur) {
            float* pr = &g_pnum[bcur * HID_CH + lane * 8];
            red4(pr, r[0], r[1], r[2], r[3]);
            red4(pr + 4, r[4], r[5], r[6], r[7]);
            if (lane == 0) atomicAdd(&g_denom[bcur], dsum);
            #pragma unroll
            for (int q = 0; q < 8; q++) r[q] = 0.f;
            dsum = 0.f;
            bcur = b;
        }
        float a = expf(g_gate[i] - fdec(g_gmax[b]));
        const float* hr = &g_h2[(size_t)i * HID_CH + lane * 8];
        float4 h0 = *(const float4*)hr;
        float4 h1 = *(const float4*)(hr + 4);
        r[0] += a * h0.x; r[1] += a * h0.y; r[2] += a * h0.z; r[3] += a * h0.w;
        r[4] += a * h1.x; r[5] += a * h1.y; r[6] += a * h1.z; r[7] += a * h1.w;
        dsum += a;
    }
    float* pr = &g_pnum[bcur * HID_CH + lane * 8];
    red4(pr, r[0], r[1], r[2], r[3]);
    red4(pr + 4, r[4], r[5], r[6], r[7]);
    if (lane == 0) atomicAdd(&g_denom[bcur], dsum);
}

// ---------------- fused pool + head: pooled = pnum/denom; logits = pooled @ Wh + bh ----------------
__global__ void __launch_bounds__(128) head_kernel(const float* __restrict__ Wh,
                                                   const float* __restrict__ bh,
                                                   float* __restrict__ out, int B) {
    __shared__ float p[8][HID_CH];
    __shared__ float dsh[8];
    int kb = blockIdx.x * 128 + threadIdx.x;
    int b0 = blockIdx.y * 8;
    int nb = min(8, B - b0);
    if (threadIdx.x < 8)
        dsh[threadIdx.x] = (threadIdx.x < nb) ? g_denom[b0 + threadIdx.x] : 1.f;
    __syncthreads();
    for (int i = threadIdx.x; i < nb * HID_CH; i += 128) {
        int g = i >> 8, c = i & 255;
        float d = dsh[g];
        float pv = (d > 0.f) ? g_pnum[(b0 + g) * HID_CH + c] / d : 0.f;
        p[g][c] = pv;
        if (blockIdx.x == 0) out[(size_t)B * K_CLS + (b0 + g) * HID_CH + c] = pv;
    }
    __syncthreads();
    if (kb >= K_CLS) return;
    float acc[8];
    #pragma unroll
    for (int j = 0; j < 8; j++) acc[j] = 0.f;
    #pragma unroll 4
    for (int c = 0; c < HID_CH; c++) {
        float wv = Wh[(size_t)c * K_CLS + kb];
        #pragma unroll
        for (int j = 0; j < 8; j++) acc[j] += p[j][c] * wv;
    }
    float bv = bh[kb];
    for (int j = 0; j < nb; j++)
        out[(size_t)(b0 + j) * K_CLS + kb] = acc[j] + bv;
}

// ---------------- launch ----------------
extern "C" void kernel_launch(void* const* d_in, const int* in_sizes, int n_in,
                              void* d_out, int out_size) {
    const float* x     = (const float*)d_in[0];
    const void*  ei    = d_in[1];
    const float* eattr = (const float*)d_in[2];
    const void*  batch = d_in[3];
    const float* We    = (const float*)d_in[4];
    const float* be    = (const float*)d_in[5];
    const float* b1    = (const float*)d_in[7];
    const float* b2    = (const float*)d_in[9];
    const float* bg1   = (const float*)d_in[11];
    const float* Wg2   = (const float*)d_in[12];
    const float* bg2   = (const float*)d_in[13];
    const float* Wh    = (const float*)d_in[14];
    const float* bh    = (const float*)d_in[15];
    float* out = (float*)d_out;

    int n = in_sizes[0] / IN_CH;
    int E = in_sizes[2] / ED_CH;
    int B = out_size / (K_CLS + HID_CH);

    cudaFuncSetAttribute(edge_mma, cudaFuncAttributeMaxDynamicSharedMemorySize, EDGE_DSM);
    cudaFuncSetAttribute(fused_mlp, cudaFuncAttributeMaxDynamicSharedMemorySize, FUSE_DSM);

    prep_kernel<<<dim3(8, 8, 4), dim3(32, 8)>>>(We, (const float*)d_in[6],
                                                (const float*)d_in[8], (const float*)d_in[10]);
    init_kernel<<<2048, 256>>>(x, (const int*)ei, n);

    edge_mma<<<(E + 127) / 128, 256, EDGE_DSM>>>(eattr, ei, x, be, E);

    int mb = (n + 127) / 128;
    fused_mlp<<<mb, 512, FUSE_DSM>>>(b1, b2, bg1, Wg2, bg2, batch, n);

    gsum_kernel<<<400, 256>>>(batch, n);
    head_kernel<<<dim3(8, (B + 7) / 8), 128>>>(Wh, bh, out, B);
}

// round 10
// speedup vs baseline: 1.0605x; 1.0605x over previous
#include <cuda_runtime.h>
#include <cuda_fp16.h>
#include <math.h>

#define IN_CH  128
#define ED_CH  64
#define HID_CH 256
#define K_CLS  1000
#define MAXN   50000
#define MAXB   128

// transposed fp16 weights: [n][k] layouts (offsets in half elements)
#define WE_T_OFF  0          // 128 x 64
#define W1_T_OFF  8192       // 256 x 128
#define W2_T_OFF  40960      // 256 x 256
#define WG1_T_OFF 106496     // 128 x 256

#define STAGE_BYTES 36864    // one (A 18KB + B 18KB) fp16 stage
#define EDGE_DSM    (36864 + 32768)   // 1 stage + 128x128 fp16 x-stage -> 3 CTAs/SM

// ---------------- scratch (static device globals; no allocation) ----------------
__device__ float    g_agg[MAXN * IN_CH];     // init = x, edge adds messages -> becomes h
__device__ __half   g_x16[MAXN * IN_CH];     // fp16 copy of x for edge gather
__device__ __half   g_t[MAXN * HID_CH];      // fp16 activations
__device__ float    g_h2[MAXN * HID_CH];
__device__ float    g_gate[MAXN];
__device__ unsigned g_gmax[MAXB];
__device__ float    g_denom[MAXB];
__device__ float    g_pnum[MAXB * HID_CH];
__device__ __half   g_wt[139264];
__device__ int      g_is64;

// ---------------- helpers ----------------
__device__ __forceinline__ unsigned fenc(float f) {
    unsigned u = __float_as_uint(f);
    return (u & 0x80000000u) ? ~u : (u | 0x80000000u);
}
__device__ __forceinline__ float fdec(unsigned u) {
    return __uint_as_float((u & 0x80000000u) ? (u ^ 0x80000000u) : ~u);
}
__device__ __forceinline__ void red4(float* p, float a, float b, float c, float d) {
    asm volatile("red.global.add.v4.f32 [%0], {%1,%2,%3,%4};"
                 :: "l"(p), "f"(a), "f"(b), "f"(c), "f"(d) : "memory");
}
__device__ __forceinline__ long long load_index(const void* p, long i, int is64) {
    if (is64) return ((const long long*)p)[i];
    return (long long)((const int*)p)[i];
}
__device__ __forceinline__ unsigned f2h2(float a, float b) {
    __half2 h = __floats2half2_rn(a, b);
    return *(unsigned*)&h;
}
__device__ __forceinline__ void mma16(float* c, const unsigned* a, const unsigned* b) {
    asm volatile("mma.sync.aligned.m16n8k16.row.col.f32.f16.f16.f32 "
                 "{%0,%1,%2,%3}, {%4,%5,%6,%7}, {%8,%9}, {%0,%1,%2,%3};"
                 : "+f"(c[0]), "+f"(c[1]), "+f"(c[2]), "+f"(c[3])
                 : "r"(a[0]), "r"(a[1]), "r"(a[2]), "r"(a[3]), "r"(b[0]), "r"(b[1]));
}
__device__ __forceinline__ void ldsm4(unsigned* r, unsigned addr) {
    asm volatile("ldmatrix.sync.aligned.m8n8.x4.shared.b16 {%0,%1,%2,%3}, [%4];"
                 : "=r"(r[0]), "=r"(r[1]), "=r"(r[2]), "=r"(r[3]) : "r"(addr));
}
__device__ __forceinline__ void cpasync16(unsigned saddr, const void* g) {
    asm volatile("cp.async.cg.shared.global [%0], [%1], 16;" :: "r"(saddr), "l"(g) : "memory");
}
__device__ __forceinline__ void cp_commit() {
    asm volatile("cp.async.commit_group;" ::: "memory");
}
template <int N> __device__ __forceinline__ void cp_wait() {
    asm volatile("cp.async.wait_group %0;" :: "n"(N) : "memory");
}

// fragment smem byte-addresses for ldmatrix (A: [m][k] rows, B: [n][k] rows; stride 72 halves)
__device__ __forceinline__ void frag_addrs(unsigned as_b, unsigned bs_b, int lane,
                                           int wm, int wn, unsigned* aa, unsigned* bb) {
    #pragma unroll
    for (int mi = 0; mi < 2; mi++)
        aa[mi] = as_b + ((wm * 32 + mi * 16 + (lane & 15)) * 72 + (lane >> 4) * 8) * 2;
    #pragma unroll
    for (int nj = 0; nj < 4; nj++)
        bb[nj] = bs_b + ((wn * 64 + nj * 16 + (lane & 7) + ((lane >> 4) & 1) * 8) * 72
                         + ((lane >> 3) & 1) * 8) * 2;
}

// ---------------- weight prep: Wt16[n][k] = half(W[k][n]) ----------------
__global__ void prep_kernel(const float* __restrict__ We, const float* __restrict__ W1,
                            const float* __restrict__ W2, const float* __restrict__ Wg1) {
    __shared__ float t[32][33];
    const float* W; int K, N, off;
    switch (blockIdx.z) {
        case 0: W = We;  K = ED_CH;  N = IN_CH;  off = WE_T_OFF;  break;
        case 1: W = W1;  K = IN_CH;  N = HID_CH; off = W1_T_OFF;  break;
        case 2: W = W2;  K = HID_CH; N = HID_CH; off = W2_T_OFF;  break;
        default:W = Wg1; K = HID_CH; N = 128;    off = WG1_T_OFF; break;
    }
    int n0 = blockIdx.x * 32, k0 = blockIdx.y * 32;
    if (n0 >= N || k0 >= K) return;
    __half* dst = g_wt + off;
    for (int i = threadIdx.y; i < 32; i += 8)
        t[i][threadIdx.x] = W[(size_t)(k0 + i) * N + n0 + threadIdx.x];
    __syncthreads();
    for (int i = threadIdx.y; i < 32; i += 8)
        dst[(size_t)(n0 + i) * K + k0 + threadIdx.x] = __float2half(t[threadIdx.x][i]);
}

// ---------------- init: g_agg = x, g_x16 = half(x), zero accumulators, sniff dtype ----------------
__global__ void init_kernel(const float* __restrict__ x, const int* __restrict__ ei, int n) {
    int stride = gridDim.x * blockDim.x;
    int i = blockIdx.x * blockDim.x + threadIdx.x;
    int n4 = n * IN_CH / 4;
    for (int j = i; j < n4; j += stride) {
        float4 v = ((const float4*)x)[j];
        ((float4*)g_agg)[j] = v;
        ((uint2*)g_x16)[j] = make_uint2(f2h2(v.x, v.y), f2h2(v.z, v.w));
    }
    if (i < MAXB * HID_CH) g_pnum[i] = 0.f;
    if (i < MAXB) { g_denom[i] = 0.f; g_gmax[i] = 0u; }
    if (i == 0) {
        int nz = 0;
        #pragma unroll 8
        for (int k = 0; k < 256; k++) nz += (ei[2 * k + 1] != 0);
        g_is64 = (nz < 16) ? 1 : 0;
    }
}

// ---------------- edge phase: fp16 MMA + fp16 cp.async x-prefetch + fused relu/scatter ----------------
__global__ void __launch_bounds__(256) edge_mma(
    const float* __restrict__ eattr, const void* __restrict__ ei,
    const float* __restrict__ be, int E)
{
    extern __shared__ char dsm[];
    __half* AsH = (__half*)dsm;                    // [128*72]
    float*  Cs  = (float*)dsm;                     // overlay [64*132]
    __half* Xs  = (__half*)(dsm + STAGE_BYTES);    // [128*128] fp16
    __shared__ int s_src[128], s_dst[128];

    const int tid = threadIdx.x;
    const int lane = tid & 31, warp = tid >> 5;
    const int wm = warp & 3, wn = warp >> 2;
    const int r0 = lane >> 2, c0 = lane & 3;
    const int eb = blockIdx.x * 128;
    const int is64 = g_is64;
    const __half* Wt = g_wt + WE_T_OFF;

    unsigned as_b = (unsigned)__cvta_generic_to_shared(dsm);
    unsigned bs_b = as_b + 18432;
    unsigned xs_b = as_b + STAGE_BYTES;
    unsigned aa[2], bb[4];
    frag_addrs(as_b, bs_b, lane, wm, wn, aa, bb);

    if (tid < 128) {
        int eg = eb + tid;
        if (eg < E) {
            s_src[tid] = (int)load_index(ei, eg, is64);
            s_dst[tid] = (int)load_index(ei, (long)E + eg, is64);
        } else { s_src[tid] = 0; s_dst[tid] = 0; }
    }

    // B: We_t (128n x 64k halves), group 0
    #pragma unroll
    for (int i = 0; i < 4; i++) {
        int f = tid + i * 256;
        int n = f >> 3, kk = (f & 7) * 8;
        cpasync16(bs_b + (n * 72 + kk) * 2, &Wt[(size_t)n * ED_CH + kk]);
    }
    cp_commit();

    // A: edge_attr (128 x 64), f32 -> half2 into smem
    #pragma unroll
    for (int i = 0; i < 4; i++) {
        int f = tid + i * 256;
        int row = f >> 3, kk = (f & 7) * 8;
        int eg = eb + row;
        float4 v0 = make_float4(0.f, 0.f, 0.f, 0.f), v1 = v0;
        if (eg < E) {
            v0 = *(const float4*)&eattr[(size_t)eg * ED_CH + kk];
            v1 = *(const float4*)&eattr[(size_t)eg * ED_CH + kk + 4];
        }
        uint4 h;
        h.x = f2h2(v0.x, v0.y); h.y = f2h2(v0.z, v0.w);
        h.z = f2h2(v1.x, v1.y); h.w = f2h2(v1.z, v1.w);
        *(uint4*)&AsH[row * 72 + kk] = h;
    }
    __syncthreads();   // s_src visible to all

    // x16[src] prefetch: 128 rows x 256B via cp.async, group 1 (hidden under MMA)
    #pragma unroll
    for (int i = 0; i < 8; i++) {
        int f = tid + i * 256;
        int row = f >> 4, seg = f & 15;
        cpasync16(xs_b + (row * 128 + seg * 8) * 2, &g_x16[(size_t)s_src[row] * IN_CH + seg * 8]);
    }
    cp_commit();

    cp_wait<1>();      // B arrived (x may still be in flight)
    __syncthreads();

    float acc[2][8][4];
    #pragma unroll
    for (int mi = 0; mi < 2; mi++)
        #pragma unroll
        for (int ni = 0; ni < 8; ni++)
            #pragma unroll
            for (int q = 0; q < 4; q++) acc[mi][ni][q] = 0.f;

    #pragma unroll
    for (int ks = 0; ks < 4; ks++) {
        unsigned a[2][4], b[4][4];
        ldsm4(a[0], aa[0] + ks * 32);
        ldsm4(a[1], aa[1] + ks * 32);
        #pragma unroll
        for (int j = 0; j < 4; j++) ldsm4(b[j], bb[j] + ks * 32);
        #pragma unroll
        for (int mi = 0; mi < 2; mi++)
            #pragma unroll
            for (int ni = 0; ni < 8; ni++)
                mma16(acc[mi][ni], a[mi], &b[ni >> 1][(ni & 1) * 2]);
    }
    cp_wait<0>();      // x arrived
    __syncthreads();   // MMA smem reads done -> Cs overlay safe

    const float4 bev = *(const float4*)&be[lane * 4];

    // epilogue in 2 phases of 64 edge-rows (Cs overlays A/B stage; Xs separate)
    #pragma unroll
    for (int p = 0; p < 2; p++) {
        if ((wm >> 1) == p) {
            #pragma unroll
            for (int mi = 0; mi < 2; mi++)
                #pragma unroll
                for (int ni = 0; ni < 8; ni++) {
                    int r = (wm & 1) * 32 + mi * 16 + r0;
                    int col = wn * 64 + ni * 8 + 2 * c0;
                    Cs[r * 132 + col]           = acc[mi][ni][0];
                    Cs[r * 132 + col + 1]       = acc[mi][ni][1];
                    Cs[(r + 8) * 132 + col]     = acc[mi][ni][2];
                    Cs[(r + 8) * 132 + col + 1] = acc[mi][ni][3];
                }
        }
        __syncthreads();
        #pragma unroll
        for (int half = 0; half < 2; half++) {
            #pragma unroll
            for (int j = 0; j < 4; j++) {
                int el = warp * 8 + half * 4 + j;
                int eg = eb + p * 64 + el;
                if (eg < E) {
                    int d = s_dst[p * 64 + el];
                    float4 cv = *(const float4*)&Cs[el * 132 + lane * 4];
                    uint2 xu = *(uint2*)&Xs[(p * 64 + el) * 128 + lane * 4];
                    float2 xlo = __half22float2(*(__half2*)&xu.x);
                    float2 xhi = __half22float2(*(__half2*)&xu.y);
                    red4(&g_agg[(size_t)d * IN_CH + lane * 4],
                         fmaxf(cv.x + bev.x + xlo.x, 0.f),
                         fmaxf(cv.y + bev.y + xlo.y, 0.f),
                         fmaxf(cv.z + bev.z + xhi.x, 0.f),
                         fmaxf(cv.w + bev.w + xhi.y, 0.f));
                }
            }
        }
        __syncthreads();
    }
}

// ---------------- fp16 tensor-core GEMM for node MLPs (pipelined; one tile per CTA) ----------------
// MODE 0: t16 = relu(h @ W1 + b1)   K=128 N=256   A = g_agg f32 (cvt in stage)  2-stage
// MODE 1: h2  =      t @ W2 + b2    K=256 N=256   A = g_t fp16 via cp.async      3-stage
// MODE 2: gate = relu(h2 @ Wg1 + bg1) @ Wg2 + bg2  K=256 N=128  register gate epi 2-stage
template <int MODE>
__global__ void __launch_bounds__(256) gemm_mma(const float* __restrict__ bias,
                                                const float* __restrict__ Wg2,
                                                const float* __restrict__ bg2,
                                                const void* __restrict__ batch, int M)
{
    constexpr int K = (MODE == 0) ? 128 : 256;
    constexpr int N = (MODE == 2) ? 128 : 256;
    constexpr int NK = K / 64;
    constexpr int STAGES = (MODE == 1) ? 3 : 2;
    constexpr int AHEAD = STAGES - 1;
    const float* __restrict__ A = (MODE == 0) ? g_agg : g_h2;   // f32 A (MODE 0/2)
    const __half* Wt = g_wt + ((MODE == 0) ? W1_T_OFF : (MODE == 1) ? W2_T_OFF : WG1_T_OFF);

    extern __shared__ char dsm[];

    const int tid = threadIdx.x;
    const int lane = tid & 31, warp = tid >> 5;
    const int wm = warp & 3, wn = warp >> 2;
    const int r0 = lane >> 2, c0 = lane & 3;
    const int bm = blockIdx.y * 128, bn = blockIdx.x * 128;

    unsigned as_b = (unsigned)__cvta_generic_to_shared(dsm);
    unsigned bs_b = as_b + 18432;
    unsigned aa[2], bb[4];
    frag_addrs(as_b, bs_b, lane, wm, wn, aa, bb);

    float acc[2][8][4];
    #pragma unroll
    for (int mi = 0; mi < 2; mi++)
        #pragma unroll
        for (int ni = 0; ni < 8; ni++)
            #pragma unroll
            for (int q = 0; q < 4; q++) acc[mi][ni][q] = 0.f;

    auto issue_chunk = [&](int c, int s) {
        unsigned sb = (unsigned)(s * STAGE_BYTES);
        #pragma unroll
        for (int i = 0; i < 4; i++) {
            int f = tid + i * 256;
            int n = f >> 3, kk = (f & 7) * 8;
            cpasync16(bs_b + sb + (n * 72 + kk) * 2, &Wt[(size_t)(bn + n) * K + c * 64 + kk]);
        }
        if constexpr (MODE == 1) {
            #pragma unroll
            for (int i = 0; i < 4; i++) {
                int f = tid + i * 256;
                int row = f >> 3, kk = (f & 7) * 8;
                int gm = bm + row; if (gm >= M) gm = M - 1;   // clamped read; store guarded
                cpasync16(as_b + sb + (row * 72 + kk) * 2,
                          &g_t[(size_t)gm * K + c * 64 + kk]);
            }
        } else {
            #pragma unroll
            for (int i = 0; i < 4; i++) {
                int f = tid + i * 256;
                int row = f >> 3, kk = (f & 7) * 8;
                int gm = bm + row;
                float4 v0 = make_float4(0.f, 0.f, 0.f, 0.f), v1 = v0;
                if (gm < M) {
                    v0 = *(const float4*)&A[(size_t)gm * K + c * 64 + kk];
                    v1 = *(const float4*)&A[(size_t)gm * K + c * 64 + kk + 4];
                }
                uint4 h;
                h.x = f2h2(v0.x, v0.y); h.y = f2h2(v0.z, v0.w);
                h.z = f2h2(v1.x, v1.y); h.w = f2h2(v1.z, v1.w);
                *(uint4*)(dsm + sb + (row * 72 + kk) * 2) = h;
            }
        }
        cp_commit();
    };

    #pragma unroll
    for (int i = 0; i < AHEAD && i < NK; i++) issue_chunk(i, i);

    #pragma unroll
    for (int c = 0; c < NK; c++) {
        if (c + AHEAD < NK) issue_chunk(c + AHEAD, (c + AHEAD) % STAGES);
        int rem = ((c + AHEAD < NK) ? (c + AHEAD) : (NK - 1)) - c;
        if (rem >= 2) cp_wait<2>(); else if (rem == 1) cp_wait<1>(); else cp_wait<0>();
        __syncthreads();
        unsigned sb = (unsigned)((c % STAGES) * STAGE_BYTES);
        #pragma unroll
        for (int ks = 0; ks < 4; ks++) {
            unsigned a[2][4], b[4][4];
            ldsm4(a[0], aa[0] + sb + ks * 32);
            ldsm4(a[1], aa[1] + sb + ks * 32);
            #pragma unroll
            for (int j = 0; j < 4; j++) ldsm4(b[j], bb[j] + sb + ks * 32);
            #pragma unroll
            for (int mi = 0; mi < 2; mi++)
                #pragma unroll
                for (int ni = 0; ni < 8; ni++)
                    mma16(acc[mi][ni], a[mi], &b[ni >> 1][(ni & 1) * 2]);
        }
        __syncthreads();
    }

    if constexpr (MODE == 0) {
        #pragma unroll
        for (int mi = 0; mi < 2; mi++)
            #pragma unroll
            for (int ni = 0; ni < 8; ni++) {
                int row = bm + wm * 32 + mi * 16 + r0;
                int col = bn + wn * 64 + ni * 8 + 2 * c0;
                float bx = bias[col], by = bias[col + 1];
                float v0 = fmaxf(acc[mi][ni][0] + bx, 0.f);
                float v1 = fmaxf(acc[mi][ni][1] + by, 0.f);
                float v2 = fmaxf(acc[mi][ni][2] + bx, 0.f);
                float v3 = fmaxf(acc[mi][ni][3] + by, 0.f);
                if (row < M)     *(__half2*)&g_t[(size_t)row * N + col]       = __floats2half2_rn(v0, v1);
                if (row + 8 < M) *(__half2*)&g_t[(size_t)(row + 8) * N + col] = __floats2half2_rn(v2, v3);
            }
    } else if constexpr (MODE == 1) {
        #pragma unroll
        for (int mi = 0; mi < 2; mi++)
            #pragma unroll
            for (int ni = 0; ni < 8; ni++) {
                int row = bm + wm * 32 + mi * 16 + r0;
                int col = bn + wn * 64 + ni * 8 + 2 * c0;
                float bx = bias[col], by = bias[col + 1];
                float v0 = acc[mi][ni][0] + bx, v1 = acc[mi][ni][1] + by;
                float v2 = acc[mi][ni][2] + bx, v3 = acc[mi][ni][3] + by;
                if (row < M)     *(float2*)&g_h2[(size_t)row * N + col]       = make_float2(v0, v1);
                if (row + 8 < M) *(float2*)&g_h2[(size_t)(row + 8) * N + col] = make_float2(v2, v3);
            }
    } else {
        // register-space gate: per-row dot of relu(acc+bias) with Wg2, shfl over c0, smem partials
        __shared__ float part[2][128];
        #pragma unroll
        for (int mi = 0; mi < 2; mi++) {
            float s_lo = 0.f, s_hi = 0.f;
            #pragma unroll
            for (int ni = 0; ni < 8; ni++) {
                int col = wn * 64 + ni * 8 + 2 * c0;
                float bx = __ldg(&bias[col]), by = __ldg(&bias[col + 1]);
                float wx = __ldg(&Wg2[col]),  wy = __ldg(&Wg2[col + 1]);
                s_lo += fmaxf(acc[mi][ni][0] + bx, 0.f) * wx
                      + fmaxf(acc[mi][ni][1] + by, 0.f) * wy;
                s_hi += fmaxf(acc[mi][ni][2] + bx, 0.f) * wx
                      + fmaxf(acc[mi][ni][3] + by, 0.f) * wy;
            }
            s_lo += __shfl_xor_sync(0xffffffffu, s_lo, 1);
            s_lo += __shfl_xor_sync(0xffffffffu, s_lo, 2);
            s_hi += __shfl_xor_sync(0xffffffffu, s_hi, 1);
            s_hi += __shfl_xor_sync(0xffffffffu, s_hi, 2);
            if (c0 == 0) {
                part[wn][wm * 32 + mi * 16 + r0]     = s_lo;
                part[wn][wm * 32 + mi * 16 + r0 + 8] = s_hi;
            }
        }
        __syncthreads();
        if (tid < 128) {
            int row = bm + tid;
            if (row < M) {
                float g = part[0][tid] + part[1][tid] + bg2[0];
                g_gate[row] = g;
                int b = (int)load_index(batch, row, g_is64);
                atomicMax(&g_gmax[b], fenc(g));
            }
        }
    }
}

// ---------------- softmax numerator + weighted sum: warp strips with run-length flush ----------------
__global__ void gsum_kernel(const void* __restrict__ batch, int n) {
    int w = (blockIdx.x * blockDim.x + threadIdx.x) >> 5;
    int lane = threadIdx.x & 31;
    int W = (gridDim.x * blockDim.x) >> 5;
    int L = (n + W - 1) / W;
    int s0 = w * L, e0 = min(s0 + L, n);
    if (s0 >= e0) return;
    const int is64 = g_is64;

    int bcur = (int)load_index(batch, s0, is64);
    float r[8];
    #pragma unroll
    for (int q = 0; q < 8; q++) r[q] = 0.f;
    float dsum = 0.f;

    for (int i = s0; i < e0; i++) {
        int b = (int)load_index(batch, i, is64);
        if (b != bcur) {
            float* pr = &g_pnum[bcur * HID_CH + lane * 8];
            red4(pr, r[0], r[1], r[2], r[3]);
            red4(pr + 4, r[4], r[5], r[6], r[7]);
            if (lane == 0) atomicAdd(&g_denom[bcur], dsum);
            #pragma unroll
            for (int q = 0; q < 8; q++) r[q] = 0.f;
            dsum = 0.f;
            bcur = b;
        }
        float a = expf(g_gate[i] - fdec(g_gmax[b]));
        const float* hr = &g_h2[(size_t)i * HID_CH + lane * 8];
        float4 h0 = *(const float4*)hr;
        float4 h1 = *(const float4*)(hr + 4);
        r[0] += a * h0.x; r[1] += a * h0.y; r[2] += a * h0.z; r[3] += a * h0.w;
        r[4] += a * h1.x; r[5] += a * h1.y; r[6] += a * h1.z; r[7] += a * h1.w;
        dsum += a;
    }
    float* pr = &g_pnum[bcur * HID_CH + lane * 8];
    red4(pr, r[0], r[1], r[2], r[3]);
    red4(pr + 4, r[4], r[5], r[6], r[7]);
    if (lane == 0) atomicAdd(&g_denom[bcur], dsum);
}

// ---------------- fused pool + head: pooled = pnum/denom; logits = pooled @ Wh + bh ----------------
__global__ void __launch_bounds__(128) head_kernel(const float* __restrict__ Wh,
                                                   const float* __restrict__ bh,
                                                   float* __restrict__ out, int B) {
    __shared__ float p[8][HID_CH];
    __shared__ float dsh[8];
    int kb = blockIdx.x * 128 + threadIdx.x;
    int b0 = blockIdx.y * 8;
    int nb = min(8, B - b0);
    if (threadIdx.x < 8)
        dsh[threadIdx.x] = (threadIdx.x < nb) ? g_denom[b0 + threadIdx.x] : 1.f;
    __syncthreads();
    for (int i = threadIdx.x; i < nb * HID_CH; i += 128) {
        int g = i >> 8, c = i & 255;
        float d = dsh[g];
        float pv = (d > 0.f) ? g_pnum[(b0 + g) * HID_CH + c] / d : 0.f;
        p[g][c] = pv;
        if (blockIdx.x == 0) out[(size_t)B * K_CLS + (b0 + g) * HID_CH + c] = pv;
    }
    __syncthreads();
    if (kb >= K_CLS) return;
    float acc[8];
    #pragma unroll
    for (int j = 0; j < 8; j++) acc[j] = 0.f;
    #pragma unroll 4
    for (int c = 0; c < HID_CH; c++) {
        float wv = Wh[(size_t)c * K_CLS + kb];
        #pragma unroll
        for (int j = 0; j < 8; j++) acc[j] += p[j][c] * wv;
    }
    float bv = bh[kb];
    for (int j = 0; j < nb; j++)
        out[(size_t)(b0 + j) * K_CLS + kb] = acc[j] + bv;
}

// ---------------- launch ----------------
extern "C" void kernel_launch(void* const* d_in, const int* in_sizes, int n_in,
                              void* d_out, int out_size) {
    const float* x     = (const float*)d_in[0];
    const void*  ei    = d_in[1];
    const float* eattr = (const float*)d_in[2];
    const void*  batch = d_in[3];
    const float* We    = (const float*)d_in[4];
    const float* be    = (const float*)d_in[5];
    const float* b1    = (const float*)d_in[7];
    const float* b2    = (const float*)d_in[9];
    const float* bg1   = (const float*)d_in[11];
    const float* Wg2   = (const float*)d_in[12];
    const float* bg2   = (const float*)d_in[13];
    const float* Wh    = (const float*)d_in[14];
    const float* bh    = (const float*)d_in[15];
    float* out = (float*)d_out;

    int n = in_sizes[0] / IN_CH;
    int E = in_sizes[2] / ED_CH;
    int B = out_size / (K_CLS + HID_CH);

    const int DSM2 = 2 * STAGE_BYTES;   // 73728 (MODE 0/2)
    const int DSM3 = 3 * STAGE_BYTES;   // 110592 (MODE 1)

    cudaFuncSetAttribute(edge_mma, cudaFuncAttributeMaxDynamicSharedMemorySize, EDGE_DSM);
    cudaFuncSetAttribute(gemm_mma<0>, cudaFuncAttributeMaxDynamicSharedMemorySize, DSM2);
    cudaFuncSetAttribute(gemm_mma<1>, cudaFuncAttributeMaxDynamicSharedMemorySize, DSM3);
    cudaFuncSetAttribute(gemm_mma<2>, cudaFuncAttributeMaxDynamicSharedMemorySize, DSM2);

    prep_kernel<<<dim3(8, 8, 4), dim3(32, 8)>>>(We, (const float*)d_in[6],
                                                (const float*)d_in[8], (const float*)d_in[10]);
    init_kernel<<<2048, 256>>>(x, (const int*)ei, n);

    edge_mma<<<(E + 127) / 128, 256, EDGE_DSM>>>(eattr, ei, be, E);

    int mb = (n + 127) / 128;
    gemm_mma<0><<<dim3(2, mb), 256, DSM2>>>(b1, nullptr, nullptr, nullptr, n);
    gemm_mma<1><<<dim3(2, mb), 256, DSM3>>>(b2, nullptr, nullptr, nullptr, n);
    gemm_mma<2><<<dim3(1, mb), 256, DSM2>>>(bg1, Wg2, bg2, batch, n);

    gsum_kernel<<<400, 256>>>(batch, n);
    head_kernel<<<dim3(8, (B + 7) / 8), 128>>>(Wh, bh, out, B);
}